// round 8
// baseline (speedup 1.0000x reference)
#include <cuda_runtime.h>

// OpticalFlowLK 2048x2048 fp32. Register-rolling vertical scan, float4 per
// lane (4 columns), warp shuffles only for S/D/T neighbor and hbox ends.

#define IMH 2048
#define IMW 2048
#define ROW4 (IMW / 4)
#define STRIP 8
#define WPB 4
#define WOUT 120                 // output columns per warp (lanes 1..30 x 4)
#define NGROUPS 18               // ceil(2048/120)
#define FULL 0xffffffffu

struct P54 { float4 xx, yy, xy, xt, yt; };

__device__ __forceinline__ int rowclamp(int r) {
    if (r < 0) return 0;
    if (r == IMH) return IMH - 2;   // reflect-after
    if (r > IMH) return 0;
    return r;
}

__device__ __forceinline__ float4 f4add(float4 a, float4 b) {
    return make_float4(a.x + b.x, a.y + b.y, a.z + b.z, a.w + b.w);
}
__device__ __forceinline__ P54 p5add(const P54& a, const P54& b) {
    P54 r;
    r.xx = f4add(a.xx, b.xx); r.yy = f4add(a.yy, b.yy); r.xy = f4add(a.xy, b.xy);
    r.xt = f4add(a.xt, b.xt); r.yt = f4add(a.yt, b.yt);
    return r;
}

// Gradients scaled 2x vs reference (0.5 dropped): all tensor sums scale 4x
// uniformly, so u, v and the det==0 set are unchanged.
__device__ __forceinline__ P54 prodrow4(const float4& tP, const float4& bP,
                                        const float4& tN, const float4& bN) {
    float S0 = (tP.x + bP.x) + (tN.x + bN.x);
    float S1 = (tP.y + bP.y) + (tN.y + bN.y);
    float S2 = (tP.z + bP.z) + (tN.z + bN.z);
    float S3 = (tP.w + bP.w) + (tN.w + bN.w);
    float D0 = (bP.x - tP.x) + (bN.x - tN.x);
    float D1 = (bP.y - tP.y) + (bN.y - tN.y);
    float D2 = (bP.z - tP.z) + (bN.z - tN.z);
    float D3 = (bP.w - tP.w) + (bN.w - tN.w);
    float T0 = (tN.x + bN.x) - (tP.x + bP.x);
    float T1 = (tN.y + bN.y) - (tP.y + bP.y);
    float T2 = (tN.z + bN.z) - (tP.z + bP.z);
    float T3 = (tN.w + bN.w) - (tP.w + bP.w);
    float S4 = __shfl_down_sync(FULL, S0, 1);
    float D4 = __shfl_down_sync(FULL, D0, 1);
    float T4 = __shfl_down_sync(FULL, T0, 1);
    float rx0 = S1 - S0, rx1 = S2 - S1, rx2 = S3 - S2, rx3 = S4 - S3;
    float ry0 = D0 + D1, ry1 = D1 + D2, ry2 = D2 + D3, ry3 = D3 + D4;
    float rt0 = T0 + T1, rt1 = T1 + T2, rt2 = T2 + T3, rt3 = T3 + T4;
    P54 q;
    q.xx = make_float4(rx0 * rx0, rx1 * rx1, rx2 * rx2, rx3 * rx3);
    q.yy = make_float4(ry0 * ry0, ry1 * ry1, ry2 * ry2, ry3 * ry3);
    q.xy = make_float4(rx0 * ry0, rx1 * ry1, rx2 * ry2, rx3 * ry3);
    q.xt = make_float4(rt0 * rx0, rt1 * rx1, rt2 * rx2, rt3 * rx3);
    q.yt = make_float4(rt0 * ry0, rt1 * ry1, rt2 * ry2, rt3 * ry3);
    return q;
}

__device__ __forceinline__ float4 hbox4(float4 V) {
    float pv = __shfl_up_sync(FULL, V.w, 1);
    float nv = __shfl_down_sync(FULL, V.x, 1);
    return make_float4(pv + V.x + V.y, V.x + V.y + V.z,
                       V.y + V.z + V.w, V.z + V.w + nv);
}

__device__ __forceinline__ void solve1(float Sxx, float Syy, float Sxy,
                                       float Sxt, float Syt,
                                       float& u, float& v) {
    float det = Sxx * Syy - Sxy * Sxy;
    u = 0.f; v = 0.f;
    if (det != 0.f) {
        float inv = __fdividef(1.0f, det);
        u = (Syy * Sxt - Sxy * Syt) * inv;
        v = (Sxx * Syt - Sxy * Sxt) * inv;
    }
}

// ---------------- edge helpers (scalar, fully clamped) ----------------

__device__ __forceinline__ void loadrow_e(const float* __restrict__ prev,
                                          const float* __restrict__ next,
                                          size_t rb, const int* cc,
                                          float* p, float* n) {
    #pragma unroll
    for (int k = 0; k < 4; k++) {
        p[k] = prev[rb + cc[k]];
        n[k] = next[rb + cc[k]];
    }
}

__device__ __forceinline__ P54 prodrow_e4(const float* tp, const float* bp,
                                          const float* tn, const float* bn,
                                          const bool* pv) {
    float S[5], D[5], T[5];
    #pragma unroll
    for (int k = 0; k < 4; k++) {
        float sP = tp[k] + bp[k], dP = bp[k] - tp[k];
        float sN = tn[k] + bn[k], dN = bn[k] - tn[k];
        S[k] = sP + sN; D[k] = dP + dN; T[k] = sN - sP;
    }
    S[4] = __shfl_down_sync(FULL, S[0], 1);
    D[4] = __shfl_down_sync(FULL, D[0], 1);
    T[4] = __shfl_down_sync(FULL, T[0], 1);
    float xx[4], yy[4], xy[4], xt[4], yt[4];
    #pragma unroll
    for (int k = 0; k < 4; k++) {
        float rx = S[k + 1] - S[k];
        float ry = D[k] + D[k + 1];
        float rt = T[k] + T[k + 1];
        xx[k] = pv[k] ? rx * rx : 0.f;
        yy[k] = pv[k] ? ry * ry : 0.f;
        xy[k] = pv[k] ? rx * ry : 0.f;
        xt[k] = pv[k] ? rt * rx : 0.f;
        yt[k] = pv[k] ? rt * ry : 0.f;
    }
    P54 q;
    q.xx = make_float4(xx[0], xx[1], xx[2], xx[3]);
    q.yy = make_float4(yy[0], yy[1], yy[2], yy[3]);
    q.xy = make_float4(xy[0], xy[1], xy[2], xy[3]);
    q.xt = make_float4(xt[0], xt[1], xt[2], xt[3]);
    q.yt = make_float4(yt[0], yt[1], yt[2], yt[3]);
    return q;
}

__global__ __launch_bounds__(32 * WPB)
void lk_flow_kernel(const float* __restrict__ prev,
                    const float* __restrict__ next,
                    float* __restrict__ out) {
    const int lane = threadIdx.x;
    const int g = blockIdx.x * WPB + threadIdx.y;
    if (g >= NGROUPS) return;

    const int ob = g * WOUT;
    const int cb = ob - 4 + 4 * lane;   // this lane's 4 columns: cb..cb+3
    const int r0 = blockIdx.y * STRIP;
    const bool storelane = (lane >= 1) && (lane <= 30);

    const bool interior = (g >= 1) && (g <= 16) &&
                          (blockIdx.y >= 1) && (blockIdx.y <= (IMH / STRIP) - 2);

    float4* outU4 = reinterpret_cast<float4*>(out);
    float4* outV4 = reinterpret_cast<float4*>(out + (size_t)IMH * IMW);

    if (interior) {
        // ---------------- FAST PATH ----------------
        const float4* P4 = reinterpret_cast<const float4*>(prev)
                           + (size_t)(r0 - 1) * ROW4 + (cb >> 2);
        const float4* N4 = reinterpret_cast<const float4*>(next)
                           + (size_t)(r0 - 1) * ROW4 + (cb >> 2);

        float4 a0p = P4[0];        float4 a0n = N4[0];
        float4 a1p = P4[ROW4];     float4 a1n = N4[ROW4];
        float4 a2p = P4[2 * ROW4]; float4 a2n = N4[2 * ROW4];
        float4 Bp  = P4[3 * ROW4]; float4 Bn  = N4[3 * ROW4];

        P54 qm = prodrow4(a0p, a1p, a0n, a1n);
        P54 q1 = prodrow4(a1p, a2p, a1n, a2n);
        P54 s01 = p5add(qm, q1);
        float4 Ap = a2p, An = a2n;

        const float4* Pf = P4 + 4 * ROW4;
        const float4* Nf = N4 + 4 * ROW4;
        size_t o = (size_t)r0 * ROW4 + (cb >> 2);

        #pragma unroll 4
        for (int it = 0; it < STRIP; ++it) {
            float4 Cp = Pf[0], Cn = Nf[0];
            Pf += ROW4; Nf += ROW4;

            P54 q2 = prodrow4(Ap, Bp, An, Bn);

            float4 Sxx = hbox4(f4add(s01.xx, q2.xx));
            float4 Syy = hbox4(f4add(s01.yy, q2.yy));
            float4 Sxy = hbox4(f4add(s01.xy, q2.xy));
            float4 Sxt = hbox4(f4add(s01.xt, q2.xt));
            float4 Syt = hbox4(f4add(s01.yt, q2.yt));

            s01 = p5add(q1, q2);
            q1 = q2;

            float4 u4, v4;
            solve1(Sxx.x, Syy.x, Sxy.x, Sxt.x, Syt.x, u4.x, v4.x);
            solve1(Sxx.y, Syy.y, Sxy.y, Sxt.y, Syt.y, u4.y, v4.y);
            solve1(Sxx.z, Syy.z, Sxy.z, Sxt.z, Syt.z, u4.z, v4.z);
            solve1(Sxx.w, Syy.w, Sxy.w, Sxt.w, Syt.w, u4.w, v4.w);

            if (storelane) {
                outU4[o] = u4;
                outV4[o] = v4;
            }
            o += ROW4;

            Ap = Bp; An = Bn;
            Bp = Cp; Bn = Cn;
        }
        return;
    }

    // ---------------- EDGE PATH (general) ----------------
    int col[4], cc[4];
    bool cv[4];
    #pragma unroll
    for (int k = 0; k < 4; k++) {
        col[k] = cb + k;
        int c = col[k];
        if (c < 0) c = 0;
        else if (c == IMW) c = IMW - 2;
        else if (c > IMW) c = 0;
        cc[k] = c;
        cv[k] = (col[k] >= 0) && (col[k] < IMW);
    }

    float t0p[4], t0n[4], t1p[4], t1n[4], t2p[4], t2n[4];
    float Bp_[4], Bn_[4];
    loadrow_e(prev, next, (size_t)rowclamp(r0 - 1) * IMW, cc, t0p, t0n);
    loadrow_e(prev, next, (size_t)r0 * IMW,               cc, t1p, t1n);
    loadrow_e(prev, next, (size_t)(r0 + 1) * IMW,         cc, t2p, t2n);
    loadrow_e(prev, next, (size_t)(r0 + 2) * IMW,         cc, Bp_, Bn_);

    bool pv[4];
    #pragma unroll
    for (int k = 0; k < 4; k++) pv[k] = cv[k] && (r0 > 0);
    P54 qa = prodrow_e4(t0p, t1p, t0n, t1n, pv);
    P54 qb = prodrow_e4(t1p, t2p, t1n, t2n, cv);
    P54 s01 = p5add(qa, qb);
    P54 q1 = qb;

    float Ap_[4], An_[4];
    #pragma unroll
    for (int k = 0; k < 4; k++) { Ap_[k] = t2p[k]; An_[k] = t2n[k]; }

    for (int r = r0; r < r0 + STRIP; ++r) {
        float Cp_[4], Cn_[4];
        loadrow_e(prev, next, (size_t)rowclamp(r + 3) * IMW, cc, Cp_, Cn_);

        const bool rv = (r + 1 < IMH);
        bool pv2[4];
        #pragma unroll
        for (int k = 0; k < 4; k++) pv2[k] = cv[k] && rv;
        P54 q2 = prodrow_e4(Ap_, Bp_, An_, Bn_, pv2);

        float4 Sxx = hbox4(f4add(s01.xx, q2.xx));
        float4 Syy = hbox4(f4add(s01.yy, q2.yy));
        float4 Sxy = hbox4(f4add(s01.xy, q2.xy));
        float4 Sxt = hbox4(f4add(s01.xt, q2.xt));
        float4 Syt = hbox4(f4add(s01.yt, q2.yt));

        s01 = p5add(q1, q2);
        q1 = q2;

        float u[4], v[4];
        solve1(Sxx.x, Syy.x, Sxy.x, Sxt.x, Syt.x, u[0], v[0]);
        solve1(Sxx.y, Syy.y, Sxy.y, Sxt.y, Syt.y, u[1], v[1]);
        solve1(Sxx.z, Syy.z, Sxy.z, Sxt.z, Syt.z, u[2], v[2]);
        solve1(Sxx.w, Syy.w, Sxy.w, Sxt.w, Syt.w, u[3], v[3]);

        #pragma unroll
        for (int k = 0; k < 4; k++) {
            if (r == 0 || col[k] == 0) { u[k] = 0.f; v[k] = 0.f; }
        }

        if (storelane) {
            if (col[3] < IMW) {
                size_t o = (size_t)r * ROW4 + (cb >> 2);
                outU4[o] = make_float4(u[0], u[1], u[2], u[3]);
                outV4[o] = make_float4(v[0], v[1], v[2], v[3]);
            } else {
                #pragma unroll
                for (int k = 0; k < 4; k++) {
                    if (col[k] < IMW) {
                        size_t o = (size_t)r * IMW + col[k];
                        out[o] = u[k];
                        out[(size_t)IMH * IMW + o] = v[k];
                    }
                }
            }
        }

        #pragma unroll
        for (int k = 0; k < 4; k++) {
            Ap_[k] = Bp_[k]; An_[k] = Bn_[k];
            Bp_[k] = Cp_[k]; Bn_[k] = Cn_[k];
        }
    }
}

extern "C" void kernel_launch(void* const* d_in, const int* in_sizes, int n_in,
                              void* d_out, int out_size) {
    const float* prev = (const float*)d_in[0];
    const float* next = (const float*)d_in[1];
    float* out = (float*)d_out;
    dim3 block(32, WPB, 1);
    dim3 grid((NGROUPS + WPB - 1) / WPB, IMH / STRIP, 1);
    lk_flow_kernel<<<grid, block>>>(prev, next, out);
}